// round 2
// baseline (speedup 1.0000x reference)
#include <cuda_runtime.h>
#include <cuda_bf16.h>
#include <math.h>

// Problem sizes (fixed by the dataset)
#define B_    16
#define S_    4096
#define D2_   1024      // 2H: encoder feature dim
#define H_    512       // hidden dim / N of the scores GEMM
#define M_    (B_ * S_) // 65536 rows of the scores GEMM

// Scratch (no device allocation allowed -> __device__ globals)
__device__ float g_hproj[B_ * H_];     // hidden @ W_top + b_attn
__device__ float g_scores[B_ * S_];    // scores, then attention weights in-place

// ---------------------------------------------------------------------------
// Kernel 0: zero the atomic accumulation target
// ---------------------------------------------------------------------------
__global__ void zero_scores_kernel() {
    int i = blockIdx.x * blockDim.x + threadIdx.x;
    if (i < B_ * S_) g_scores[i] = 0.0f;
}

// ---------------------------------------------------------------------------
// Kernel 1: hproj[b][h] = b_attn[h] + sum_d hidden[b][d] * W_attn[d][h]
// (top 1024 rows of W_attn multiply the broadcast decoder hidden state)
// ---------------------------------------------------------------------------
__global__ __launch_bounds__(512) void hproj_kernel(
    const float* __restrict__ hidden,   // [B_, D2_]
    const float* __restrict__ W,        // [2*D2_, H_] row-major
    const float* __restrict__ b_attn)   // [H_]
{
    __shared__ float hid_s[D2_];
    int b = blockIdx.x;
    int h = threadIdx.x;                // 0..511
    for (int d = threadIdx.x; d < D2_; d += blockDim.x)
        hid_s[d] = hidden[b * D2_ + d];
    __syncthreads();

    float acc = b_attn[h];
    #pragma unroll 8
    for (int d = 0; d < D2_; ++d)
        acc = fmaf(hid_s[d], W[(size_t)d * H_ + h], acc);
    g_hproj[b * H_ + h] = acc;
}

// ---------------------------------------------------------------------------
// Kernel 2: the heavy GEMM + fused epilogue.
//   C[m][n] = sum_k enc[m][k] * Wb[k][n]      (M=65536, K=1024, N=512)
//   scores[m] += sum_n tanh(C[m][n] + hproj[b(m)][n]) * w_v[n]
// Tiling: 128x128x16, 256 threads, 8x8 microtile per thread.
// ---------------------------------------------------------------------------
#define BM 128
#define BN 128
#define BK 16

__global__ __launch_bounds__(256) void scores_kernel(
    const float* __restrict__ enc,   // [M_, D2_] row-major (flattened [B,S,2H])
    const float* __restrict__ Wb,    // [D2_, H_] = W_attn + D2_*H_
    const float* __restrict__ wv)    // [H_]
{
    __shared__ float As[BK][BM + 8];   // +8 floats keeps float4 alignment (544B rows)
    __shared__ float Bs[BK][BN];
    __shared__ float hp_s[BN];
    __shared__ float wv_s[BN];

    const int mtile = blockIdx.x;      // 0..511
    const int ntile = blockIdx.y;      // 0..3
    const int tid   = threadIdx.x;
    const int tx    = tid & 15;
    const int ty    = tid >> 4;

    const float* Ablk = enc + (size_t)mtile * BM * D2_;
    const float* Bblk = Wb + ntile * BN;

    float acc[8][8];
    #pragma unroll
    for (int i = 0; i < 8; ++i)
        #pragma unroll
        for (int j = 0; j < 8; ++j) acc[i][j] = 0.0f;

    for (int kb = 0; kb < D2_ / BK; ++kb) {
        // Load A tile (128 rows x 16 cols), transpose into As[k][m].
        #pragma unroll
        for (int i = 0; i < 2; ++i) {
            int lin = tid * 2 + i;          // 0..511 float4 slots
            int r   = lin >> 2;             // row 0..127
            int c4  = lin & 3;              // which float4 in the 16-col strip
            float4 v = *(const float4*)(Ablk + (size_t)r * D2_ + kb * BK + c4 * 4);
            As[c4 * 4 + 0][r] = v.x;
            As[c4 * 4 + 1][r] = v.y;
            As[c4 * 4 + 2][r] = v.z;
            As[c4 * 4 + 3][r] = v.w;
        }
        // Load B tile (16 rows x 128 cols), direct.
        #pragma unroll
        for (int i = 0; i < 2; ++i) {
            int lin = tid * 2 + i;          // 0..511 float4 slots
            int r   = lin >> 5;             // row 0..15
            int c4  = lin & 31;             // float4 col 0..31
            float4 v = *(const float4*)(Bblk + (size_t)(kb * BK + r) * H_ + c4 * 4);
            *(float4*)&Bs[r][c4 * 4] = v;
        }
        __syncthreads();

        #pragma unroll
        for (int k = 0; k < BK; ++k) {
            float a[8], bb[8];
            float4 a0 = *(const float4*)&As[k][ty * 8];
            float4 a1 = *(const float4*)&As[k][ty * 8 + 4];
            a[0]=a0.x; a[1]=a0.y; a[2]=a0.z; a[3]=a0.w;
            a[4]=a1.x; a[5]=a1.y; a[6]=a1.z; a[7]=a1.w;
            float4 b0 = *(const float4*)&Bs[k][tx * 8];
            float4 b1 = *(const float4*)&Bs[k][tx * 8 + 4];
            bb[0]=b0.x; bb[1]=b0.y; bb[2]=b0.z; bb[3]=b0.w;
            bb[4]=b1.x; bb[5]=b1.y; bb[6]=b1.z; bb[7]=b1.w;
            #pragma unroll
            for (int i = 0; i < 8; ++i)
                #pragma unroll
                for (int j = 0; j < 8; ++j)
                    acc[i][j] = fmaf(a[i], bb[j], acc[i][j]);
        }
        __syncthreads();
    }

    // Epilogue: tanh(C + hproj) * w_v, row-reduce, atomic into scores.
    const int b = (mtile * BM) >> 12;   // 128 rows never straddle a batch (4096 | tiles)
    if (tid < BN) {
        hp_s[tid] = g_hproj[b * H_ + ntile * BN + tid];
        wv_s[tid] = wv[ntile * BN + tid];
    }
    __syncthreads();

    #pragma unroll
    for (int i = 0; i < 8; ++i) {
        float rowsum = 0.0f;
        #pragma unroll
        for (int j = 0; j < 8; ++j) {
            float e = tanhf(acc[i][j] + hp_s[tx * 8 + j]);
            rowsum = fmaf(e, wv_s[tx * 8 + j], rowsum);
        }
        // reduce across the 16 tx lanes (xor stays within each 16-lane half-warp)
        #pragma unroll
        for (int off = 8; off >= 1; off >>= 1)
            rowsum += __shfl_xor_sync(0xffffffffu, rowsum, off);
        if (tx == 0)
            atomicAdd(&g_scores[mtile * BM + ty * 8 + i], rowsum);
    }
}

// ---------------------------------------------------------------------------
// Kernel 3: softmax over S per batch, in place in g_scores.
// ---------------------------------------------------------------------------
__global__ __launch_bounds__(256) void softmax_kernel() {
    __shared__ float red[256];
    const int b   = blockIdx.x;
    const int tid = threadIdx.x;
    float* sc = g_scores + b * S_;

    float m = -1e30f;
    for (int s = tid; s < S_; s += 256) m = fmaxf(m, sc[s]);
    red[tid] = m; __syncthreads();
    for (int off = 128; off >= 1; off >>= 1) {
        if (tid < off) red[tid] = fmaxf(red[tid], red[tid + off]);
        __syncthreads();
    }
    const float mx = red[0];
    __syncthreads();

    float sum = 0.0f;
    for (int s = tid; s < S_; s += 256) sum += expf(sc[s] - mx);
    red[tid] = sum; __syncthreads();
    for (int off = 128; off >= 1; off >>= 1) {
        if (tid < off) red[tid] += red[tid + off];
        __syncthreads();
    }
    const float inv = 1.0f / red[0];
    __syncthreads();

    for (int s = tid; s < S_; s += 256) sc[s] = expf(sc[s] - mx) * inv;
}

// ---------------------------------------------------------------------------
// Kernel 4: context[b][d] = sum_s attn[b][s] * enc[b][s][d]  (memory-bound)
// Grid: (B_, D2_/128). 256 threads: 8 s-subgroups x 32 lanes x float4.
// ---------------------------------------------------------------------------
__global__ __launch_bounds__(256) void context_kernel(
    const float* __restrict__ enc, float* __restrict__ out)
{
    __shared__ float attn_s[S_];          // 16 KB
    __shared__ float red[8][128];         // 4 KB

    const int b  = blockIdx.x;
    const int dc = blockIdx.y;            // 0..7, 128 d-columns each
    for (int s = threadIdx.x; s < S_; s += 256)
        attn_s[s] = g_scores[b * S_ + s];
    __syncthreads();

    const int tsub = threadIdx.x >> 5;    // 0..7
    const int lane = threadIdx.x & 31;
    const float* base = enc + (size_t)b * S_ * D2_ + dc * 128 + lane * 4;

    float4 acc = make_float4(0.f, 0.f, 0.f, 0.f);
    #pragma unroll 8
    for (int s = tsub; s < S_; s += 8) {
        float a   = attn_s[s];
        float4 e  = *(const float4*)(base + (size_t)s * D2_);
        acc.x = fmaf(a, e.x, acc.x);
        acc.y = fmaf(a, e.y, acc.y);
        acc.z = fmaf(a, e.z, acc.z);
        acc.w = fmaf(a, e.w, acc.w);
    }
    *(float4*)&red[tsub][lane * 4] = acc;
    __syncthreads();

    if (threadIdx.x < 128) {
        float s = 0.0f;
        #pragma unroll
        for (int t = 0; t < 8; ++t) s += red[t][threadIdx.x];
        out[b * D2_ + dc * 128 + threadIdx.x] = s;
    }
}

// ---------------------------------------------------------------------------
// Launch
// ---------------------------------------------------------------------------
extern "C" void kernel_launch(void* const* d_in, const int* in_sizes, int n_in,
                              void* d_out, int out_size) {
    const float* hidden = (const float*)d_in[0];   // [16, 1024]
    const float* enc    = (const float*)d_in[1];   // [16, 4096, 1024]
    const float* W      = (const float*)d_in[2];   // [2048, 512]
    const float* b_attn = (const float*)d_in[3];   // [512]
    const float* wv     = (const float*)d_in[4];   // [512]
    float* out = (float*)d_out;                    // [16, 1024]

    zero_scores_kernel<<<(B_ * S_ + 1023) / 1024, 1024>>>();
    hproj_kernel<<<B_, 512>>>(hidden, W, b_attn);
    scores_kernel<<<dim3(M_ / BM, H_ / BN), 256>>>(enc, W + (size_t)D2_ * H_, wv);
    softmax_kernel<<<B_, 256>>>();
    context_kernel<<<dim3(B_, D2_ / 128), 256>>>(enc, out);
}

// round 4
// speedup vs baseline: 2.3700x; 2.3700x over previous
#include <cuda_runtime.h>
#include <cuda_fp16.h>
#include <math.h>
#include <stdint.h>

// Problem sizes (fixed)
#define B_    16
#define S_    4096
#define D2_   1024      // 2H
#define H_    512
#define M_    (B_ * S_)

// Scratch
__device__ float g_hproj[B_ * H_];
__device__ float g_partial[4 * M_];          // per-ntile partial row sums
__device__ __half g_W16[D2_ * H_];           // W bottom, fp16, [k][n] row-major

// smem pitches (halves)
#define PA 40     // A tile rows: 32 halves + 8 pad (80 B, 16B-aligned, conflict-free ldmatrix)
#define PB 136    // B tile rows: 128 halves + 8 pad (272 B)

// ---------------------------------------------------------------------------
// helpers
// ---------------------------------------------------------------------------
__device__ __forceinline__ uint32_t smem_u32(const void* p) {
    uint32_t a;
    asm("{ .reg .u64 t; cvta.to.shared.u64 t, %1; cvt.u32.u64 %0, t; }" : "=r"(a) : "l"(p));
    return a;
}
__device__ __forceinline__ void ldmx4(uint32_t addr, uint32_t& r0, uint32_t& r1,
                                      uint32_t& r2, uint32_t& r3) {
    asm volatile("ldmatrix.sync.aligned.m8n8.x4.shared.b16 {%0,%1,%2,%3}, [%4];"
                 : "=r"(r0), "=r"(r1), "=r"(r2), "=r"(r3) : "r"(addr));
}
__device__ __forceinline__ void ldmx4t(uint32_t addr, uint32_t& r0, uint32_t& r1,
                                       uint32_t& r2, uint32_t& r3) {
    asm volatile("ldmatrix.sync.aligned.m8n8.x4.trans.shared.b16 {%0,%1,%2,%3}, [%4];"
                 : "=r"(r0), "=r"(r1), "=r"(r2), "=r"(r3) : "r"(addr));
}
__device__ __forceinline__ void mma16816(float* c, uint32_t a0, uint32_t a1,
                                         uint32_t a2, uint32_t a3,
                                         uint32_t b0, uint32_t b1) {
    asm volatile(
        "mma.sync.aligned.m16n8k16.row.col.f32.f16.f16.f32 "
        "{%0,%1,%2,%3},{%4,%5,%6,%7},{%8,%9},{%0,%1,%2,%3};"
        : "+f"(c[0]), "+f"(c[1]), "+f"(c[2]), "+f"(c[3])
        : "r"(a0), "r"(a1), "r"(a2), "r"(a3), "r"(b0), "r"(b1));
}

// ---------------------------------------------------------------------------
// hproj[b][h] = b_attn[h] + hidden[b] @ W_top[:,h]   (fp32, tiny)
// ---------------------------------------------------------------------------
__global__ __launch_bounds__(512) void hproj_kernel(
    const float* __restrict__ hidden, const float* __restrict__ W,
    const float* __restrict__ b_attn)
{
    __shared__ float hid_s[D2_];
    int b = blockIdx.x, h = threadIdx.x;
    for (int d = threadIdx.x; d < D2_; d += blockDim.x)
        hid_s[d] = hidden[b * D2_ + d];
    __syncthreads();
    float acc = b_attn[h];
    #pragma unroll 8
    for (int d = 0; d < D2_; ++d)
        acc = fmaf(hid_s[d], W[(size_t)d * H_ + h], acc);
    g_hproj[b * H_ + h] = acc;
}

// ---------------------------------------------------------------------------
// pack W bottom [1024,512] fp32 -> fp16 [k][n]
// ---------------------------------------------------------------------------
__global__ __launch_bounds__(256) void wpack_kernel(const float* __restrict__ W) {
    int idx = blockIdx.x * 256 + threadIdx.x;   // 0..524287
    g_W16[idx] = __float2half(W[(size_t)D2_ * H_ + idx]);
}

// ---------------------------------------------------------------------------
// scores GEMM: C = enc_f16 @ Wb_f16 (M=65536, K=1024, N=512), CTA 128x128x32.
// Epilogue: partial[m] = sum_n tanh(C+hp)*wv over this CTA's 128 n-cols.
// ---------------------------------------------------------------------------
__global__ __launch_bounds__(256, 1) void scores_kernel(
    const float* __restrict__ enc, const float* __restrict__ wv)
{
    __shared__ __half As[128 * PA];
    __shared__ __half Bs[32 * PB];
    __shared__ float  hp_s[128], wv_s[128], red[256];

    const int tid = threadIdx.x, wid = tid >> 5, lane = tid & 31;
    const int mtile = blockIdx.x >> 2;     // ntile-fastest for L2 A reuse
    const int ntile = blockIdx.x & 3;
    const int b = mtile >> 5;

    if (tid < 128) {
        hp_s[tid] = g_hproj[b * H_ + ntile * 128 + tid];
        wv_s[tid] = wv[ntile * 128 + tid];
    }

    const float* Abase = enc + (size_t)mtile * 128 * D2_;
    const __half* Bbase = g_W16 + ntile * 128;

    // global-load thread mapping
    const int ar  = tid >> 1;                 // A row 0..127 (2 threads/row)
    const int af0 = (tid & 1) * 4;            // first float4 idx within 8/row
    const int br  = tid >> 3;                 // B row 0..31 (8 threads/row)
    const int bu0 = (tid & 7) * 2;            // first uint4 idx within 16/row

    float4 av[4];
    uint4  bv[2];

    auto load_regs = [&](int kc) {
        const float* Ap = Abase + (size_t)ar * D2_ + kc * 32;
        #pragma unroll
        for (int i = 0; i < 4; ++i) av[i] = *(const float4*)(Ap + (af0 + i) * 4);
        const uint4* Bp = (const uint4*)(Bbase + (size_t)(kc * 32 + br) * H_);
        #pragma unroll
        for (int i = 0; i < 2; ++i) bv[i] = Bp[bu0 + i];
    };
    auto store_smem = [&]() {
        #pragma unroll
        for (int i = 0; i < 4; ++i) {
            __half2* dst = (__half2*)&As[ar * PA + (af0 + i) * 4];
            dst[0] = __floats2half2_rn(av[i].x, av[i].y);
            dst[1] = __floats2half2_rn(av[i].z, av[i].w);
        }
        uint4* brow = (uint4*)&Bs[br * PB];
        #pragma unroll
        for (int i = 0; i < 2; ++i) brow[bu0 + i] = bv[i];
    };

    // accumulators: 2 m-atoms x 8 n-atoms x 4 f32
    float acc[2][8][4];
    #pragma unroll
    for (int i = 0; i < 2; ++i)
        #pragma unroll
        for (int j = 0; j < 8; ++j)
            #pragma unroll
            for (int t = 0; t < 4; ++t) acc[i][j][t] = 0.0f;

    // ldmatrix base addresses
    const int m_base = (wid >> 1) * 32;
    const int n_base = (wid & 1) * 64;
    const uint32_t As_b = smem_u32(As), Bs_b = smem_u32(Bs);
    const uint32_t a_addr = As_b + ((m_base + (lane & 15)) * PA + (lane >> 4) * 8) * 2;
    const uint32_t b_addr = Bs_b + (((lane & 7) + ((lane >> 3) & 1) * 8) * PB
                                    + n_base + (lane >> 4) * 8) * 2;

    // prologue
    load_regs(0);
    store_smem();
    __syncthreads();

    for (int kc = 0; kc < 32; ++kc) {
        if (kc + 1 < 32) load_regs(kc + 1);

        #pragma unroll
        for (int ks = 0; ks < 2; ++ks) {
            uint32_t Af[2][4], Bf[4][4];
            #pragma unroll
            for (int ma = 0; ma < 2; ++ma)
                ldmx4(a_addr + (ma * 16 * PA + ks * 16) * 2,
                      Af[ma][0], Af[ma][1], Af[ma][2], Af[ma][3]);
            #pragma unroll
            for (int g = 0; g < 4; ++g)
                ldmx4t(b_addr + (ks * 16 * PB + g * 16) * 2,
                       Bf[g][0], Bf[g][1], Bf[g][2], Bf[g][3]);
            #pragma unroll
            for (int ma = 0; ma < 2; ++ma)
                #pragma unroll
                for (int j = 0; j < 8; ++j)
                    mma16816(acc[ma][j], Af[ma][0], Af[ma][1], Af[ma][2], Af[ma][3],
                             Bf[j >> 1][(j & 1) * 2], Bf[j >> 1][(j & 1) * 2 + 1]);
        }
        __syncthreads();
        if (kc + 1 < 32) {
            store_smem();
            __syncthreads();
        }
    }

    // ---- epilogue ----
    #pragma unroll
    for (int ma = 0; ma < 2; ++ma) {
        float rs0 = 0.0f, rs1 = 0.0f;   // rows m_base+ma*16+(lane>>2) and +8
        #pragma unroll
        for (int j = 0; j < 8; ++j) {
            int col = n_base + j * 8 + (lane & 3) * 2;
            float h0 = hp_s[col], h1 = hp_s[col + 1];
            float w0 = wv_s[col], w1 = wv_s[col + 1];
            rs0 = fmaf(tanhf(acc[ma][j][0] + h0), w0, rs0);
            rs0 = fmaf(tanhf(acc[ma][j][1] + h1), w1, rs0);
            rs1 = fmaf(tanhf(acc[ma][j][2] + h0), w0, rs1);
            rs1 = fmaf(tanhf(acc[ma][j][3] + h1), w1, rs1);
        }
        // reduce over the 4 lanes sharing a row (lane&3)
        #pragma unroll
        for (int off = 1; off <= 2; off <<= 1) {
            rs0 += __shfl_xor_sync(0xffffffffu, rs0, off);
            rs1 += __shfl_xor_sync(0xffffffffu, rs1, off);
        }
        if ((lane & 3) == 0) {
            int r0 = m_base + ma * 16 + (lane >> 2);
            red[r0 * 2 + (wid & 1)] = rs0;
            red[(r0 + 8) * 2 + (wid & 1)] = rs1;
        }
    }
    __syncthreads();
    if (tid < 128)
        g_partial[(size_t)ntile * M_ + mtile * 128 + tid] = red[tid * 2] + red[tid * 2 + 1];
}

// ---------------------------------------------------------------------------
// fused softmax + context. grid (B_, 8), 256 threads.
// ---------------------------------------------------------------------------
__global__ __launch_bounds__(256) void context_kernel(
    const float* __restrict__ enc, float* __restrict__ out)
{
    __shared__ float attn_s[S_];
    __shared__ float red2[256];
    __shared__ float redc[8][128];

    const int b = blockIdx.x, dc = blockIdx.y, tid = threadIdx.x;

    float lmax = -1e30f;
    for (int s = tid; s < S_; s += 256) {
        size_t m = (size_t)b * S_ + s;
        float v = g_partial[m] + g_partial[M_ + m] +
                  g_partial[2 * (size_t)M_ + m] + g_partial[3 * (size_t)M_ + m];
        attn_s[s] = v;
        lmax = fmaxf(lmax, v);
    }
    red2[tid] = lmax; __syncthreads();
    for (int off = 128; off >= 1; off >>= 1) {
        if (tid < off) red2[tid] = fmaxf(red2[tid], red2[tid + off]);
        __syncthreads();
    }
    const float mx = red2[0];
    __syncthreads();

    float lsum = 0.0f;
    for (int s = tid; s < S_; s += 256) {
        float e = __expf(attn_s[s] - mx);
        attn_s[s] = e;
        lsum += e;
    }
    red2[tid] = lsum; __syncthreads();
    for (int off = 128; off >= 1; off >>= 1) {
        if (tid < off) red2[tid] += red2[tid + off];
        __syncthreads();
    }
    const float inv = 1.0f / red2[0];
    __syncthreads();
    for (int s = tid; s < S_; s += 256) attn_s[s] *= inv;
    __syncthreads();

    const int tsub = tid >> 5, lane = tid & 31;
    const float* base = enc + (size_t)b * S_ * D2_ + dc * 128 + lane * 4;
    float4 acc = make_float4(0.f, 0.f, 0.f, 0.f);
    #pragma unroll 8
    for (int s = tsub; s < S_; s += 8) {
        float a  = attn_s[s];
        float4 e = *(const float4*)(base + (size_t)s * D2_);
        acc.x = fmaf(a, e.x, acc.x);
        acc.y = fmaf(a, e.y, acc.y);
        acc.z = fmaf(a, e.z, acc.z);
        acc.w = fmaf(a, e.w, acc.w);
    }
    *(float4*)&redc[tsub][lane * 4] = acc;
    __syncthreads();
    if (tid < 128) {
        float s = 0.0f;
        #pragma unroll
        for (int t = 0; t < 8; ++t) s += redc[t][tid];
        out[b * D2_ + dc * 128 + tid] = s;
    }
}

// ---------------------------------------------------------------------------
// Launch
// ---------------------------------------------------------------------------
extern "C" void kernel_launch(void* const* d_in, const int* in_sizes, int n_in,
                              void* d_out, int out_size) {
    const float* hidden = (const float*)d_in[0];
    const float* enc    = (const float*)d_in[1];
    const float* W      = (const float*)d_in[2];
    const float* b_attn = (const float*)d_in[3];
    const float* wv     = (const float*)d_in[4];
    float* out = (float*)d_out;

    hproj_kernel<<<B_, 512>>>(hidden, W, b_attn);
    wpack_kernel<<<(D2_ * H_) / 256, 256>>>(W);
    scores_kernel<<<(M_ / 128) * 4, 256>>>(enc, wv);
    context_kernel<<<dim3(B_, 8), 256>>>(enc, out);
}

// round 5
// speedup vs baseline: 2.9759x; 1.2556x over previous
#include <cuda_runtime.h>
#include <cuda_fp16.h>
#include <math.h>
#include <stdint.h>

// Problem sizes (fixed)
#define B_    16
#define S_    4096
#define D2_   1024      // 2H
#define H_    512
#define M_    (B_ * S_)

// Scratch
__device__ float g_hproj[B_ * H_];
__device__ float g_partial[4 * M_];          // per-ntile partial row sums
__device__ float g_scores[M_];               // softmaxed attention
__device__ float g_ctx[4 * B_ * D2_];        // per-schunk context partials
__device__ __half g_W16[D2_ * H_];           // W bottom, fp16, [k][n] row-major

// smem pitches (halves)
#define PA 40     // A rows: 32 halves + 8 pad
#define PB 136    // B rows: 128 halves + 8 pad (272 B, 16B-aligned)

// ---------------------------------------------------------------------------
// helpers
// ---------------------------------------------------------------------------
__device__ __forceinline__ uint32_t smem_u32(const void* p) {
    uint32_t a;
    asm("{ .reg .u64 t; cvta.to.shared.u64 t, %1; cvt.u32.u64 %0, t; }" : "=r"(a) : "l"(p));
    return a;
}
__device__ __forceinline__ void ldmx4(uint32_t addr, uint32_t& r0, uint32_t& r1,
                                      uint32_t& r2, uint32_t& r3) {
    asm volatile("ldmatrix.sync.aligned.m8n8.x4.shared.b16 {%0,%1,%2,%3}, [%4];"
                 : "=r"(r0), "=r"(r1), "=r"(r2), "=r"(r3) : "r"(addr));
}
__device__ __forceinline__ void ldmx4t(uint32_t addr, uint32_t& r0, uint32_t& r1,
                                       uint32_t& r2, uint32_t& r3) {
    asm volatile("ldmatrix.sync.aligned.m8n8.x4.trans.shared.b16 {%0,%1,%2,%3}, [%4];"
                 : "=r"(r0), "=r"(r1), "=r"(r2), "=r"(r3) : "r"(addr));
}
__device__ __forceinline__ void mma16816(float* c, uint32_t a0, uint32_t a1,
                                         uint32_t a2, uint32_t a3,
                                         uint32_t b0, uint32_t b1) {
    asm volatile(
        "mma.sync.aligned.m16n8k16.row.col.f32.f16.f16.f32 "
        "{%0,%1,%2,%3},{%4,%5,%6,%7},{%8,%9},{%0,%1,%2,%3};"
        : "+f"(c[0]), "+f"(c[1]), "+f"(c[2]), "+f"(c[3])
        : "r"(a0), "r"(a1), "r"(a2), "r"(a3), "r"(b0), "r"(b1));
}
__device__ __forceinline__ void cp16(uint32_t dst, const void* src) {
    asm volatile("cp.async.cg.shared.global [%0], [%1], 16;" :: "r"(dst), "l"(src));
}

// ---------------------------------------------------------------------------
// hproj[b][h] = b_attn[h] + hidden[b] @ W_top[:,h]   (fp32, tiny)
// ---------------------------------------------------------------------------
__global__ __launch_bounds__(512) void hproj_kernel(
    const float* __restrict__ hidden, const float* __restrict__ W,
    const float* __restrict__ b_attn)
{
    __shared__ float hid_s[D2_];
    int b = blockIdx.x, h = threadIdx.x;
    for (int d = threadIdx.x; d < D2_; d += blockDim.x)
        hid_s[d] = hidden[b * D2_ + d];
    __syncthreads();
    float acc = b_attn[h];
    #pragma unroll 8
    for (int d = 0; d < D2_; ++d)
        acc = fmaf(hid_s[d], W[(size_t)d * H_ + h], acc);
    g_hproj[b * H_ + h] = acc;
}

// ---------------------------------------------------------------------------
// pack W bottom [1024,512] fp32 -> fp16 [k][n]
// ---------------------------------------------------------------------------
__global__ __launch_bounds__(256) void wpack_kernel(const float* __restrict__ W) {
    int idx = blockIdx.x * 256 + threadIdx.x;
    g_W16[idx] = __float2half(W[(size_t)D2_ * H_ + idx]);
}

// ---------------------------------------------------------------------------
// scores GEMM: C = enc_f16 @ Wb_f16, CTA 128x128x32, double-buffered.
// ---------------------------------------------------------------------------
__global__ __launch_bounds__(256, 1) void scores_kernel(
    const float* __restrict__ enc, const float* __restrict__ wv)
{
    __shared__ __half As[2][128 * PA];     // 2 x 10 KB
    __shared__ __half Bs[2][32 * PB];      // 2 x 8.5 KB
    __shared__ float  hp_s[128], wv_s[128], red[256];

    const int tid = threadIdx.x, wid = tid >> 5, lane = tid & 31;
    const int mtile = blockIdx.x >> 2;     // ntile-fastest for L2 A reuse
    const int ntile = blockIdx.x & 3;
    const int b = mtile >> 5;

    if (tid < 128) {
        hp_s[tid] = g_hproj[b * H_ + ntile * 128 + tid];
        wv_s[tid] = wv[ntile * 128 + tid];
    }

    const float* Abase = enc + (size_t)mtile * 128 * D2_;
    const __half* Bbase = g_W16 + ntile * 128;

    // A: 2 threads/row, 4 float4 each
    const int ar  = tid >> 1;
    const int af0 = (tid & 1) * 4;
    // B cp.async: 512 16B-chunks, 2 per thread
    const int b_row0 = (tid * 2) >> 4;          // row of first chunk
    const int b_c0   = (tid * 2) & 15;          // chunk idx within row

    const uint32_t Bs_u32 = smem_u32(Bs);

    float4 av[4];
    auto load_A_regs = [&](int kc) {
        const float* Ap = Abase + (size_t)ar * D2_ + kc * 32;
        #pragma unroll
        for (int i = 0; i < 4; ++i) av[i] = *(const float4*)(Ap + (af0 + i) * 4);
    };
    auto store_A = [&](int buf) {
        #pragma unroll
        for (int i = 0; i < 4; ++i) {
            __half2* dst = (__half2*)&As[buf][ar * PA + (af0 + i) * 4];
            dst[0] = __floats2half2_rn(av[i].x, av[i].y);
            dst[1] = __floats2half2_rn(av[i].z, av[i].w);
        }
    };
    auto issue_B = [&](int kc, int buf) {
        #pragma unroll
        for (int i = 0; i < 2; ++i) {
            int row = b_row0 + ((b_c0 + i) >> 4) - ((b_c0 + i) == 16 ? 0 : 0); // b_c0 in {0..14 even}, no carry
            int c   = b_c0 + i;
            const __half* src = Bbase + (size_t)(kc * 32 + row) * H_ + c * 8;
            uint32_t dst = Bs_u32 + (uint32_t)(buf * 32 * PB + row * PB + c * 8) * 2;
            cp16(dst, src);
        }
        asm volatile("cp.async.commit_group;" ::: "memory");
    };

    // accumulators: 2 m-atoms x 8 n-atoms x 4 f32
    float acc[2][8][4];
    #pragma unroll
    for (int i = 0; i < 2; ++i)
        #pragma unroll
        for (int j = 0; j < 8; ++j)
            #pragma unroll
            for (int t = 0; t < 4; ++t) acc[i][j][t] = 0.0f;

    const int m_base = (wid >> 1) * 32;
    const int n_base = (wid & 1) * 64;
    const uint32_t As_u32 = smem_u32(As);
    const uint32_t a_off = ((m_base + (lane & 15)) * PA + (lane >> 4) * 8) * 2;
    const uint32_t b_off = (((lane & 7) + ((lane >> 3) & 1) * 8) * PB
                            + n_base + (lane >> 4) * 8) * 2;

    // prologue: chunk 0 into buffer 0
    issue_B(0, 0);
    load_A_regs(0);
    store_A(0);
    asm volatile("cp.async.wait_group 0;" ::: "memory");
    __syncthreads();

    for (int kc = 0; kc < 32; ++kc) {
        const int buf = kc & 1;
        if (kc + 1 < 32) {
            issue_B(kc + 1, buf ^ 1);
            load_A_regs(kc + 1);
        }
        const uint32_t a_base = As_u32 + (uint32_t)buf * 128 * PA * 2 + a_off;
        const uint32_t b_base = Bs_u32 + (uint32_t)buf * 32 * PB * 2 + b_off;
        #pragma unroll
        for (int ks = 0; ks < 2; ++ks) {
            uint32_t Af[2][4], Bf[4][4];
            #pragma unroll
            for (int ma = 0; ma < 2; ++ma)
                ldmx4(a_base + (ma * 16 * PA + ks * 16) * 2,
                      Af[ma][0], Af[ma][1], Af[ma][2], Af[ma][3]);
            #pragma unroll
            for (int g = 0; g < 4; ++g)
                ldmx4t(b_base + (ks * 16 * PB + g * 16) * 2,
                       Bf[g][0], Bf[g][1], Bf[g][2], Bf[g][3]);
            #pragma unroll
            for (int ma = 0; ma < 2; ++ma)
                #pragma unroll
                for (int j = 0; j < 8; ++j)
                    mma16816(acc[ma][j], Af[ma][0], Af[ma][1], Af[ma][2], Af[ma][3],
                             Bf[j >> 1][(j & 1) * 2], Bf[j >> 1][(j & 1) * 2 + 1]);
        }
        if (kc + 1 < 32) {
            store_A(buf ^ 1);
            asm volatile("cp.async.wait_group 0;" ::: "memory");
        }
        __syncthreads();
    }

    // ---- epilogue (validated mapping) ----
    #pragma unroll
    for (int ma = 0; ma < 2; ++ma) {
        float rs0 = 0.0f, rs1 = 0.0f;
        #pragma unroll
        for (int j = 0; j < 8; ++j) {
            int col = n_base + j * 8 + (lane & 3) * 2;
            float h0 = hp_s[col], h1 = hp_s[col + 1];
            float w0 = wv_s[col], w1 = wv_s[col + 1];
            rs0 = fmaf(tanhf(acc[ma][j][0] + h0), w0, rs0);
            rs0 = fmaf(tanhf(acc[ma][j][1] + h1), w1, rs0);
            rs1 = fmaf(tanhf(acc[ma][j][2] + h0), w0, rs1);
            rs1 = fmaf(tanhf(acc[ma][j][3] + h1), w1, rs1);
        }
        #pragma unroll
        for (int off = 1; off <= 2; off <<= 1) {
            rs0 += __shfl_xor_sync(0xffffffffu, rs0, off);
            rs1 += __shfl_xor_sync(0xffffffffu, rs1, off);
        }
        if ((lane & 3) == 0) {
            int r0 = m_base + ma * 16 + (lane >> 2);
            red[r0 * 2 + (wid & 1)] = rs0;
            red[(r0 + 8) * 2 + (wid & 1)] = rs1;
        }
    }
    __syncthreads();
    if (tid < 128)
        g_partial[(size_t)ntile * M_ + mtile * 128 + tid] = red[tid * 2] + red[tid * 2 + 1];
}

// ---------------------------------------------------------------------------
// softmax: fold 4 n-tile partials, softmax over S, write g_scores. grid=B_.
// ---------------------------------------------------------------------------
__global__ __launch_bounds__(256) void softmax_kernel() {
    __shared__ float sc_s[S_];
    __shared__ float red2[256];
    const int b = blockIdx.x, tid = threadIdx.x;

    float lmax = -1e30f;
    for (int s = tid; s < S_; s += 256) {
        size_t m = (size_t)b * S_ + s;
        float v = g_partial[m] + g_partial[M_ + m] +
                  g_partial[2 * (size_t)M_ + m] + g_partial[3 * (size_t)M_ + m];
        sc_s[s] = v;
        lmax = fmaxf(lmax, v);
    }
    red2[tid] = lmax; __syncthreads();
    for (int off = 128; off >= 1; off >>= 1) {
        if (tid < off) red2[tid] = fmaxf(red2[tid], red2[tid + off]);
        __syncthreads();
    }
    const float mx = red2[0];
    __syncthreads();
    float lsum = 0.0f;
    for (int s = tid; s < S_; s += 256) {
        float e = __expf(sc_s[s] - mx);
        sc_s[s] = e;
        lsum += e;
    }
    red2[tid] = lsum; __syncthreads();
    for (int off = 128; off >= 1; off >>= 1) {
        if (tid < off) red2[tid] += red2[tid + off];
        __syncthreads();
    }
    const float inv = 1.0f / red2[0];
    __syncthreads();
    for (int s = tid; s < S_; s += 256)
        g_scores[b * S_ + s] = sc_s[s] * inv;
}

// ---------------------------------------------------------------------------
// context partials: grid (B_, 8 dcols, 4 schunks), 256 threads.
// ---------------------------------------------------------------------------
__global__ __launch_bounds__(256) void context_kernel(const float* __restrict__ enc)
{
    __shared__ float attn_s[1024];
    __shared__ float redc[8][128];

    const int b = blockIdx.x, dc = blockIdx.y, sc = blockIdx.z, tid = threadIdx.x;
    const int s0 = sc * 1024;

    for (int s = tid; s < 1024; s += 256)
        attn_s[s] = g_scores[b * S_ + s0 + s];
    __syncthreads();

    const int tsub = tid >> 5, lane = tid & 31;
    const float* base = enc + (size_t)b * S_ * D2_ + (size_t)s0 * D2_
                        + dc * 128 + lane * 4;
    float4 acc = make_float4(0.f, 0.f, 0.f, 0.f);
    #pragma unroll 8
    for (int s = tsub; s < 1024; s += 8) {
        float a  = attn_s[s];
        float4 e = *(const float4*)(base + (size_t)s * D2_);
        acc.x = fmaf(a, e.x, acc.x);
        acc.y = fmaf(a, e.y, acc.y);
        acc.z = fmaf(a, e.z, acc.z);
        acc.w = fmaf(a, e.w, acc.w);
    }
    *(float4*)&redc[tsub][lane * 4] = acc;
    __syncthreads();
    if (tid < 128) {
        float s = 0.0f;
        #pragma unroll
        for (int t = 0; t < 8; ++t) s += redc[t][tid];
        g_ctx[((size_t)sc * B_ + b) * D2_ + dc * 128 + tid] = s;
    }
}

// ---------------------------------------------------------------------------
// reduce 4 context partials -> out
// ---------------------------------------------------------------------------
__global__ __launch_bounds__(256) void ctx_reduce_kernel(float* __restrict__ out) {
    int i = blockIdx.x * 256 + threadIdx.x;       // 0..16383
    out[i] = g_ctx[i] + g_ctx[B_ * D2_ + i] +
             g_ctx[2 * B_ * D2_ + i] + g_ctx[3 * B_ * D2_ + i];
}

// ---------------------------------------------------------------------------
// Launch
// ---------------------------------------------------------------------------
extern "C" void kernel_launch(void* const* d_in, const int* in_sizes, int n_in,
                              void* d_out, int out_size) {
    const float* hidden = (const float*)d_in[0];
    const float* enc    = (const float*)d_in[1];
    const float* W      = (const float*)d_in[2];
    const float* b_attn = (const float*)d_in[3];
    const float* wv     = (const float*)d_in[4];
    float* out = (float*)d_out;

    hproj_kernel<<<B_, 512>>>(hidden, W, b_attn);
    wpack_kernel<<<(D2_ * H_) / 256, 256>>>(W);
    scores_kernel<<<(M_ / 128) * 4, 256>>>(enc, wv);
    softmax_kernel<<<B_, 256>>>();
    context_kernel<<<dim3(B_, 8, 4), 256>>>(enc);
    ctx_reduce_kernel<<<(B_ * D2_) / 256, 256>>>(out);
}

// round 6
// speedup vs baseline: 4.2989x; 1.4446x over previous
#include <cuda_runtime.h>
#include <cuda_fp16.h>
#include <math.h>
#include <stdint.h>

// Problem sizes (fixed)
#define B_    16
#define S_    4096
#define D2_   1024      // 2H
#define H_    512
#define M_    (B_ * S_)

// Scratch
__device__ float g_hproj[B_ * H_];
__device__ float g_partial[4 * M_];          // per-ntile partial row sums
__device__ float g_scores[M_];               // softmaxed attention
__device__ float g_ctx[4 * B_ * D2_];        // per-schunk context partials
__device__ __half g_W16[D2_ * H_];           // W bottom, fp16, [k][n] row-major

// smem pitches (halves)
#define PA 40     // A rows: 32 halves + 8 pad
#define PB 136    // B rows: 128 halves + 8 pad (272 B, 16B-aligned)

// ---------------------------------------------------------------------------
// helpers
// ---------------------------------------------------------------------------
__device__ __forceinline__ uint32_t smem_u32(const void* p) {
    uint32_t a;
    asm("{ .reg .u64 t; cvta.to.shared.u64 t, %1; cvt.u32.u64 %0, t; }" : "=r"(a) : "l"(p));
    return a;
}
__device__ __forceinline__ void ldmx4(uint32_t addr, uint32_t& r0, uint32_t& r1,
                                      uint32_t& r2, uint32_t& r3) {
    asm volatile("ldmatrix.sync.aligned.m8n8.x4.shared.b16 {%0,%1,%2,%3}, [%4];"
                 : "=r"(r0), "=r"(r1), "=r"(r2), "=r"(r3) : "r"(addr));
}
__device__ __forceinline__ void ldmx4t(uint32_t addr, uint32_t& r0, uint32_t& r1,
                                       uint32_t& r2, uint32_t& r3) {
    asm volatile("ldmatrix.sync.aligned.m8n8.x4.trans.shared.b16 {%0,%1,%2,%3}, [%4];"
                 : "=r"(r0), "=r"(r1), "=r"(r2), "=r"(r3) : "r"(addr));
}
__device__ __forceinline__ void mma16816(float* c, uint32_t a0, uint32_t a1,
                                         uint32_t a2, uint32_t a3,
                                         uint32_t b0, uint32_t b1) {
    asm volatile(
        "mma.sync.aligned.m16n8k16.row.col.f32.f16.f16.f32 "
        "{%0,%1,%2,%3},{%4,%5,%6,%7},{%8,%9},{%0,%1,%2,%3};"
        : "+f"(c[0]), "+f"(c[1]), "+f"(c[2]), "+f"(c[3])
        : "r"(a0), "r"(a1), "r"(a2), "r"(a3), "r"(b0), "r"(b1));
}
__device__ __forceinline__ void cp16(uint32_t dst, const void* src) {
    asm volatile("cp.async.cg.shared.global [%0], [%1], 16;" :: "r"(dst), "l"(src));
}

// ---------------------------------------------------------------------------
// hproj[b][h] = b_attn[h] + hidden[b] @ W_top[:,h]   (fp32, tiny)
// ---------------------------------------------------------------------------
__global__ __launch_bounds__(512) void hproj_kernel(
    const float* __restrict__ hidden, const float* __restrict__ W,
    const float* __restrict__ b_attn)
{
    __shared__ float hid_s[D2_];
    int b = blockIdx.x, h = threadIdx.x;
    for (int d = threadIdx.x; d < D2_; d += blockDim.x)
        hid_s[d] = hidden[b * D2_ + d];
    __syncthreads();
    float acc = b_attn[h];
    #pragma unroll 8
    for (int d = 0; d < D2_; ++d)
        acc = fmaf(hid_s[d], W[(size_t)d * H_ + h], acc);
    g_hproj[b * H_ + h] = acc;
}

// ---------------------------------------------------------------------------
// pack W bottom [1024,512] fp32 -> fp16 [k][n]
// ---------------------------------------------------------------------------
__global__ __launch_bounds__(256) void wpack_kernel(const float* __restrict__ W) {
    int idx = blockIdx.x * 256 + threadIdx.x;
    g_W16[idx] = __float2half(W[(size_t)D2_ * H_ + idx]);
}

// ---------------------------------------------------------------------------
// scores GEMM: C = enc_f16 @ Wb_f16, CTA 128x128x32, double-buffered,
// 2 CTAs/SM (occupancy experiment: discriminates stall-bound vs pipe-cap).
// ---------------------------------------------------------------------------
__global__ __launch_bounds__(256, 2) void scores_kernel(
    const float* __restrict__ enc, const float* __restrict__ wv)
{
    __shared__ __half As[2][128 * PA];     // 2 x 10 KB
    __shared__ __half Bs[2][32 * PB];      // 2 x 8.5 KB
    __shared__ float  hp_s[128], wv_s[128], red[256];

    const int tid = threadIdx.x, wid = tid >> 5, lane = tid & 31;
    const int mtile = blockIdx.x >> 2;     // ntile-fastest for L2 A reuse
    const int ntile = blockIdx.x & 3;
    const int b = mtile >> 5;

    if (tid < 128) {
        hp_s[tid] = g_hproj[b * H_ + ntile * 128 + tid];
        wv_s[tid] = wv[ntile * 128 + tid];
    }

    const float* Abase = enc + (size_t)mtile * 128 * D2_;
    const __half* Bbase = g_W16 + ntile * 128;

    // A: 2 threads/row, 4 float4 each
    const int ar  = tid >> 1;
    const int af0 = (tid & 1) * 4;
    // B cp.async: 512 16B-chunks, 2 per thread
    const int b_row0 = (tid * 2) >> 4;
    const int b_c0   = (tid * 2) & 15;

    const uint32_t Bs_u32 = smem_u32(Bs);

    float4 av[4];
    auto load_A_regs = [&](int kc) {
        const float* Ap = Abase + (size_t)ar * D2_ + kc * 32;
        #pragma unroll
        for (int i = 0; i < 4; ++i) av[i] = *(const float4*)(Ap + (af0 + i) * 4);
    };
    auto store_A = [&](int buf) {
        #pragma unroll
        for (int i = 0; i < 4; ++i) {
            __half2* dst = (__half2*)&As[buf][ar * PA + (af0 + i) * 4];
            dst[0] = __floats2half2_rn(av[i].x, av[i].y);
            dst[1] = __floats2half2_rn(av[i].z, av[i].w);
        }
    };
    auto issue_B = [&](int kc, int buf) {
        #pragma unroll
        for (int i = 0; i < 2; ++i) {
            int row = b_row0;
            int c   = b_c0 + i;
            const __half* src = Bbase + (size_t)(kc * 32 + row) * H_ + c * 8;
            uint32_t dst = Bs_u32 + (uint32_t)(buf * 32 * PB + row * PB + c * 8) * 2;
            cp16(dst, src);
        }
        asm volatile("cp.async.commit_group;" ::: "memory");
    };

    float acc[2][8][4];
    #pragma unroll
    for (int i = 0; i < 2; ++i)
        #pragma unroll
        for (int j = 0; j < 8; ++j)
            #pragma unroll
            for (int t = 0; t < 4; ++t) acc[i][j][t] = 0.0f;

    const int m_base = (wid >> 1) * 32;
    const int n_base = (wid & 1) * 64;
    const uint32_t As_u32 = smem_u32(As);
    const uint32_t a_off = ((m_base + (lane & 15)) * PA + (lane >> 4) * 8) * 2;
    const uint32_t b_off = (((lane & 7) + ((lane >> 3) & 1) * 8) * PB
                            + n_base + (lane >> 4) * 8) * 2;

    // prologue
    issue_B(0, 0);
    load_A_regs(0);
    store_A(0);
    asm volatile("cp.async.wait_group 0;" ::: "memory");
    __syncthreads();

    for (int kc = 0; kc < 32; ++kc) {
        const int buf = kc & 1;
        if (kc + 1 < 32) {
            issue_B(kc + 1, buf ^ 1);
            load_A_regs(kc + 1);
        }
        const uint32_t a_base = As_u32 + (uint32_t)buf * 128 * PA * 2 + a_off;
        const uint32_t b_base = Bs_u32 + (uint32_t)buf * 32 * PB * 2 + b_off;
        #pragma unroll
        for (int ks = 0; ks < 2; ++ks) {
            uint32_t Af[2][4], Bf[4][4];
            #pragma unroll
            for (int ma = 0; ma < 2; ++ma)
                ldmx4(a_base + (ma * 16 * PA + ks * 16) * 2,
                      Af[ma][0], Af[ma][1], Af[ma][2], Af[ma][3]);
            #pragma unroll
            for (int g = 0; g < 4; ++g)
                ldmx4t(b_base + (ks * 16 * PB + g * 16) * 2,
                       Bf[g][0], Bf[g][1], Bf[g][2], Bf[g][3]);
            #pragma unroll
            for (int ma = 0; ma < 2; ++ma)
                #pragma unroll
                for (int j = 0; j < 8; ++j)
                    mma16816(acc[ma][j], Af[ma][0], Af[ma][1], Af[ma][2], Af[ma][3],
                             Bf[j >> 1][(j & 1) * 2], Bf[j >> 1][(j & 1) * 2 + 1]);
        }
        if (kc + 1 < 32) {
            store_A(buf ^ 1);
            asm volatile("cp.async.wait_group 0;" ::: "memory");
        }
        __syncthreads();
    }

    // ---- epilogue (validated mapping) ----
    #pragma unroll
    for (int ma = 0; ma < 2; ++ma) {
        float rs0 = 0.0f, rs1 = 0.0f;
        #pragma unroll
        for (int j = 0; j < 8; ++j) {
            int col = n_base + j * 8 + (lane & 3) * 2;
            float h0 = hp_s[col], h1 = hp_s[col + 1];
            float w0 = wv_s[col], w1 = wv_s[col + 1];
            rs0 = fmaf(tanhf(acc[ma][j][0] + h0), w0, rs0);
            rs0 = fmaf(tanhf(acc[ma][j][1] + h1), w1, rs0);
            rs1 = fmaf(tanhf(acc[ma][j][2] + h0), w0, rs1);
            rs1 = fmaf(tanhf(acc[ma][j][3] + h1), w1, rs1);
        }
        #pragma unroll
        for (int off = 1; off <= 2; off <<= 1) {
            rs0 += __shfl_xor_sync(0xffffffffu, rs0, off);
            rs1 += __shfl_xor_sync(0xffffffffu, rs1, off);
        }
        if ((lane & 3) == 0) {
            int r0 = m_base + ma * 16 + (lane >> 2);
            red[r0 * 2 + (wid & 1)] = rs0;
            red[(r0 + 8) * 2 + (wid & 1)] = rs1;
        }
    }
    __syncthreads();
    if (tid < 128)
        g_partial[(size_t)ntile * M_ + mtile * 128 + tid] = red[tid * 2] + red[tid * 2 + 1];
}

// ---------------------------------------------------------------------------
// softmax: fold 4 n-tile partials, softmax over S, write g_scores. grid=B_.
// ---------------------------------------------------------------------------
__global__ __launch_bounds__(512) void softmax_kernel() {
    __shared__ float sc_s[S_];
    __shared__ float red2[512];
    const int b = blockIdx.x, tid = threadIdx.x;

    float lmax = -1e30f;
    for (int s = tid; s < S_; s += 512) {
        size_t m = (size_t)b * S_ + s;
        float v = g_partial[m] + g_partial[M_ + m] +
                  g_partial[2 * (size_t)M_ + m] + g_partial[3 * (size_t)M_ + m];
        sc_s[s] = v;
        lmax = fmaxf(lmax, v);
    }
    red2[tid] = lmax; __syncthreads();
    for (int off = 256; off >= 1; off >>= 1) {
        if (tid < off) red2[tid] = fmaxf(red2[tid], red2[tid + off]);
        __syncthreads();
    }
    const float mx = red2[0];
    __syncthreads();
    float lsum = 0.0f;
    for (int s = tid; s < S_; s += 512) {
        float e = __expf(sc_s[s] - mx);
        sc_s[s] = e;
        lsum += e;
    }
    red2[tid] = lsum; __syncthreads();
    for (int off = 256; off >= 1; off >>= 1) {
        if (tid < off) red2[tid] += red2[tid + off];
        __syncthreads();
    }
    const float inv = 1.0f / red2[0];
    __syncthreads();
    for (int s = tid; s < S_; s += 512)
        g_scores[b * S_ + s] = sc_s[s] * inv;
}

// ---------------------------------------------------------------------------
// context partials: grid (B_, 8 dcols, 4 schunks), 256 threads.
// ---------------------------------------------------------------------------
__global__ __launch_bounds__(256) void context_kernel(const float* __restrict__ enc)
{
    __shared__ float attn_s[1024];
    __shared__ float redc[8][128];

    const int b = blockIdx.x, dc = blockIdx.y, sc = blockIdx.z, tid = threadIdx.x;
    const int s0 = sc * 1024;

    for (int s = tid; s < 1024; s += 256)
        attn_s[s] = g_scores[b * S_ + s0 + s];
    __syncthreads();

    const int tsub = tid >> 5, lane = tid & 31;
    const float* base = enc + (size_t)b * S_ * D2_ + (size_t)s0 * D2_
                        + dc * 128 + lane * 4;
    float4 acc = make_float4(0.f, 0.f, 0.f, 0.f);
    #pragma unroll 8
    for (int s = tsub; s < 1024; s += 8) {
        float a  = attn_s[s];
        float4 e = *(const float4*)(base + (size_t)s * D2_);
        acc.x = fmaf(a, e.x, acc.x);
        acc.y = fmaf(a, e.y, acc.y);
        acc.z = fmaf(a, e.z, acc.z);
        acc.w = fmaf(a, e.w, acc.w);
    }
    *(float4*)&redc[tsub][lane * 4] = acc;
    __syncthreads();
    if (tid < 128) {
        float s = 0.0f;
        #pragma unroll
        for (int t = 0; t < 8; ++t) s += redc[t][tid];
        g_ctx[((size_t)sc * B_ + b) * D2_ + dc * 128 + tid] = s;
    }
}

// ---------------------------------------------------------------------------
// reduce 4 context partials -> out
// ---------------------------------------------------------------------------
__global__ __launch_bounds__(256) void ctx_reduce_kernel(float* __restrict__ out) {
    int i = blockIdx.x * 256 + threadIdx.x;
    out[i] = g_ctx[i] + g_ctx[B_ * D2_ + i] +
             g_ctx[2 * B_ * D2_ + i] + g_ctx[3 * B_ * D2_ + i];
}

// ---------------------------------------------------------------------------
// Launch
// ---------------------------------------------------------------------------
extern "C" void kernel_launch(void* const* d_in, const int* in_sizes, int n_in,
                              void* d_out, int out_size) {
    const float* hidden = (const float*)d_in[0];
    const float* enc    = (const float*)d_in[1];
    const float* W      = (const float*)d_in[2];
    const float* b_attn = (const float*)d_in[3];
    const float* wv     = (const float*)d_in[4];
    float* out = (float*)d_out;

    hproj_kernel<<<B_, 512>>>(hidden, W, b_attn);
    wpack_kernel<<<(D2_ * H_) / 256, 256>>>(W);
    scores_kernel<<<(M_ / 128) * 4, 256>>>(enc, wv);
    softmax_kernel<<<B_, 512>>>();
    context_kernel<<<dim3(B_, 8, 4), 256>>>(enc);
    ctx_reduce_kernel<<<(B_ * D2_) / 256, 256>>>(out);
}